// round 14
// baseline (speedup 1.0000x reference)
#include <cuda_runtime.h>
#include <math.h>
#include <stdint.h>

#define S_   128
#define B_   32
#define E2_  1024
#define DH_  512
#define AH_  32
#define EMB_ 256
#define V_   32000
#define MAXLEN_ 48
#define XDIM_ (E2_ + EMB_)          // 1280
#define TILE_V 128
#define NBLK_B (V_ / TILE_V)        // 250

#define GI_TILES 12                 // 1536/128 row tiles
#define GI_KS    10                 // 1280/128 k-chunks
#define GH_KS    4                  // 512/128  k-chunks
#define GG_BLOCKS (GI_TILES * GI_KS + GI_TILES * GH_KS)   // 168

// ---------------- scratch (static device globals; no allocation) ----------------
__device__ float g_encp[S_ * B_ * AH_];     // enc @ W1_e.T + b1   [s][b][j]
__device__ float g_hA[B_ * DH_];            // h, normal layout [b][d] (parity)
__device__ float g_hB[B_ * DH_];
__device__ float g_hTA[DH_ * B_];           // h transposed [d][b] (parity)
__device__ float g_hTB[DH_ * B_];
__device__ float g_xT[XDIM_ * B_];          // [context|emb] transposed [k][b]
__device__ float g_gi[GI_KS * 3 * DH_ * B_];  // GI partials [ks][row][b]
__device__ float g_gh[GH_KS * 3 * DH_ * B_];  // GH partials [ks][row][b]
__device__ float g_cval[NBLK_B * B_];       // per-tile argmax candidates
__device__ int   g_cidx[NBLK_B * B_];

// ---------------- init h = 0 (both layouts) ----------------
__global__ void k_zero() {
    int i = blockIdx.x * blockDim.x + threadIdx.x;
    if (i < B_ * DH_) { g_hA[i] = 0.0f; g_hTA[i] = 0.0f; }
}

// ---------------- one-time: enc_proj[s][b][j] = enc[s,b,:] . W1[j, 512:1536] + b1[j] ----------------
__global__ void k_encproj(const float* __restrict__ enc,
                          const float* __restrict__ W1,
                          const float* __restrict__ b1) {
    int s = blockIdx.x;
    int t = threadIdx.x;           // 256
    int j = t >> 3, l = t & 7;     // 32 j-octets, 8-way k-split
    const float* w = W1 + j * (DH_ + E2_) + DH_;
    const float* es = enc + s * B_ * E2_;
    float acc[B_];
#pragma unroll
    for (int b = 0; b < B_; b++) acc[b] = 0.0f;
    for (int k = l; k < E2_; k += 8) {
        float wv = w[k];
#pragma unroll
        for (int b = 0; b < B_; b++) acc[b] += wv * es[b * E2_ + k];
    }
#pragma unroll
    for (int b = 0; b < B_; b++) {
        float v = acc[b];
        v += __shfl_down_sync(0xffffffffu, v, 4);
        v += __shfl_down_sync(0xffffffffu, v, 2);
        v += __shfl_down_sync(0xffffffffu, v, 1);
        if (l == 0) g_encp[s * B_ * AH_ + b * AH_ + j] = v + b1[j];
    }
}

// ---------------- per step: argmax-finish + embed + attention + context ----------------
// grid = B_ blocks (one per batch), 256 threads
__global__ void k_attn(int t, int parity,
                       const float* __restrict__ enc,
                       const float* __restrict__ W1,
                       const float* __restrict__ W2,
                       const float* __restrict__ b2,
                       const float* __restrict__ emb,
                       const int* __restrict__ sosp, int sosc) {
    int b   = blockIdx.x;
    int tid = threadIdx.x;

    __shared__ float hs[DH_];
    __shared__ float hp[AH_];
    __shared__ float w2s[AH_];
    __shared__ float sc[S_];
    __shared__ float red[2];
    __shared__ int   sid;
    __shared__ float rv2[256];
    __shared__ int   ri2[256];

    const float* hprev = parity ? g_hB : g_hA;

    // phase 0: finish previous step's argmax (tree reduction, first-max tie-break),
    // gather embedding into transposed x
    if (t == 0) {
        if (tid == 0) sid = sosp ? sosp[0] : sosc;
        __syncthreads();
    } else {
        rv2[tid] = (tid < NBLK_B) ? g_cval[tid * B_ + b] : -3.4e38f;
        ri2[tid] = (tid < NBLK_B) ? g_cidx[tid * B_ + b] : 0;
        __syncthreads();
#pragma unroll
        for (int s = 128; s >= 1; s >>= 1) {
            if (tid < s) {
                // strict > keeps lower slot on ties; slots are ascending vocab
                // ranges, so this reproduces jnp.argmax first-max semantics
                if (rv2[tid + s] > rv2[tid]) { rv2[tid] = rv2[tid + s]; ri2[tid] = ri2[tid + s]; }
            }
            __syncthreads();
        }
        if (tid == 0) sid = ri2[0];
        __syncthreads();
    }
    g_xT[(E2_ + tid) * B_ + b] = emb[(size_t)sid * EMB_ + tid];  // 256 threads == EMB

    // phase 1: load h, compute hproj[j] = h . W1[j, 0:512]
    for (int i = tid; i < DH_; i += 256) hs[i] = hprev[b * DH_ + i];
    if (tid < AH_) w2s[tid] = W2[tid];
    __syncthreads();
    {
        int j = tid >> 3, l = tid & 7;
        const float* w = W1 + j * (DH_ + E2_);
        float p = 0.0f;
        for (int k = l; k < DH_; k += 8) p += hs[k] * w[k];
        p += __shfl_down_sync(0xffffffffu, p, 4);
        p += __shfl_down_sync(0xffffffffu, p, 2);
        p += __shfl_down_sync(0xffffffffu, p, 1);
        if (l == 0) hp[j] = p;
    }
    __syncthreads();

    // phase 2: scores + softmax over S
    if (tid < S_) {
        const float* ep = g_encp + tid * B_ * AH_ + b * AH_;
        float v = b2[0];
#pragma unroll
        for (int j = 0; j < AH_; j++) v += fmaxf(ep[j] + hp[j], 0.0f) * w2s[j];
        sc[tid] = v;
    }
    __syncthreads();
    if (tid < 32) {
        float m = fmaxf(fmaxf(sc[tid], sc[tid + 32]), fmaxf(sc[tid + 64], sc[tid + 96]));
#pragma unroll
        for (int o = 16; o; o >>= 1) m = fmaxf(m, __shfl_xor_sync(0xffffffffu, m, o));
        if (tid == 0) red[0] = m;
    }
    __syncthreads();
    if (tid < S_) sc[tid] = expf(sc[tid] - red[0]);
    __syncthreads();
    if (tid < 32) {
        float sm = sc[tid] + sc[tid + 32] + sc[tid + 64] + sc[tid + 96];
#pragma unroll
        for (int o = 16; o; o >>= 1) sm += __shfl_xor_sync(0xffffffffu, sm, o);
        if (tid == 0) red[1] = sm;
    }
    __syncthreads();

    // phase 3: context (4 contiguous e per thread, float4 loads), write transposed
    {
        int e = tid * 4;
        float inv = 1.0f / red[1];
        const float4* ebase = reinterpret_cast<const float4*>(enc + (size_t)b * E2_ + e);
        float4 acc = make_float4(0.f, 0.f, 0.f, 0.f);
#pragma unroll 8
        for (int s0 = 0; s0 < S_; s0++) {
            float4 ev = ebase[s0 * (B_ * E2_ / 4)];
            float w = sc[s0];
            acc.x += w * ev.x; acc.y += w * ev.y; acc.z += w * ev.z; acc.w += w * ev.w;
        }
        g_xT[(e + 0) * B_ + b] = acc.x * inv;
        g_xT[(e + 1) * B_ + b] = acc.y * inv;
        g_xT[(e + 2) * B_ + b] = acc.z * inv;
        g_xT[(e + 3) * B_ + b] = acc.w * inv;
    }
}

// ---------------- per step: GRU gate GEMM (split-K, f32x2) ----------------
// GI: [1536 x 1280] @ xT[1280 x 32]   (12 row tiles x 10 k-chunks = 120 blocks)
// GH: [1536 x 512]  @ hT[512 x 32]    (12 row tiles x 4 k-chunks  = 48 blocks)
// tile 128 rows x 32 b, thread = 2v x 8b, 128-k chunk staged in smem
__global__ void __launch_bounds__(256, 2)
k_ggemm(int parity, const float* __restrict__ W_ih, const float* __restrict__ W_hh) {
    __shared__ float hs[128 * B_];      // 16 KB input chunk [k_local][b]

    int blk = blockIdx.x, tid = threadIdx.x;
    const float* W; const float* inT; float* part;
    int rowTile, ks, kstride;
    if (blk < GI_TILES * GI_KS) {
        W = W_ih; inT = g_xT; part = g_gi;
        rowTile = blk / GI_KS; ks = blk % GI_KS; kstride = XDIM_;
    } else {
        int i2 = blk - GI_TILES * GI_KS;
        W = W_hh; inT = parity ? g_hTB : g_hTA; part = g_gh;
        rowTile = i2 / GH_KS; ks = i2 % GH_KS; kstride = DH_;
    }
    int v0 = rowTile * 128, k0 = ks * 128;

    {   // stage input chunk (coalesced float4)
        const float4* src = reinterpret_cast<const float4*>(inT + k0 * B_);
        float4* dst = reinterpret_cast<float4*>(hs);
#pragma unroll
        for (int i = 0; i < 4; i++) dst[tid + 256 * i] = src[tid + 256 * i];
    }
    __syncthreads();

    int vl = (tid >> 2) * 2;
    int bb = (tid & 3) * 8;
    const float* wrow0 = W + (size_t)(v0 + vl) * kstride + k0;
    const float* wrow1 = wrow0 + kstride;

    unsigned long long a0[4] = {0ull, 0ull, 0ull, 0ull};
    unsigned long long a1[4] = {0ull, 0ull, 0ull, 0ull};

    for (int kl = 0; kl < 128; kl += 4) {
        float4 w0 = *reinterpret_cast<const float4*>(wrow0 + kl);
        float4 w1 = *reinterpret_cast<const float4*>(wrow1 + kl);
        const float* w0p = reinterpret_cast<const float*>(&w0);
        const float* w1p = reinterpret_cast<const float*>(&w1);
#pragma unroll
        for (int kk = 0; kk < 4; kk++) {
            unsigned long long w0d, w1d;
            asm("mov.b64 %0, {%1,%1};" : "=l"(w0d) : "f"(w0p[kk]));
            asm("mov.b64 %0, {%1,%1};" : "=l"(w1d) : "f"(w1p[kk]));
            const unsigned long long* hrow =
                reinterpret_cast<const unsigned long long*>(&hs[(kl + kk) * B_ + bb]);
#pragma unroll
            for (int j = 0; j < 4; j++) {
                unsigned long long hv = hrow[j];
                asm("fma.rn.f32x2 %0, %1, %2, %0;" : "+l"(a0[j]) : "l"(w0d), "l"(hv));
                asm("fma.rn.f32x2 %0, %1, %2, %0;" : "+l"(a1[j]) : "l"(w1d), "l"(hv));
            }
        }
    }

    // epilogue: write partials [ks][row][b]
    float* p0 = part + ((size_t)ks * (3 * DH_) + v0 + vl) * B_ + bb;
    float* p1 = p0 + B_;
#pragma unroll
    for (int j = 0; j < 4; j++) {
        float x0, x1, y0, y1;
        asm("mov.b64 {%0,%1}, %2;" : "=f"(x0), "=f"(x1) : "l"(a0[j]));
        asm("mov.b64 {%0,%1}, %2;" : "=f"(y0), "=f"(y1) : "l"(a1[j]));
        p0[2 * j] = x0; p0[2 * j + 1] = x1;
        p1[2 * j] = y0; p1[2 * j + 1] = y1;
    }
}

// ---------------- per step: gate combine + nonlinearity + h update ----------------
// grid 64 x 256; thread -> (d = idx>>5, b = idx&31); all gate reads coalesced over b
__global__ void k_comb(int parity,
                       const float* __restrict__ b_ih, const float* __restrict__ b_hh) {
    int idx = blockIdx.x * 256 + threadIdx.x;
    int d = idx >> 5, b = idx & 31;

    float gir = b_ih[d], giz = b_ih[DH_ + d], gin = b_ih[2 * DH_ + d];
#pragma unroll
    for (int s = 0; s < GI_KS; s++) {
        const float* gp = g_gi + (size_t)s * (3 * DH_) * B_;
        gir += gp[d * B_ + b];
        giz += gp[(DH_ + d) * B_ + b];
        gin += gp[(2 * DH_ + d) * B_ + b];
    }
    float ghr = b_hh[d], ghz = b_hh[DH_ + d], ghn = b_hh[2 * DH_ + d];
#pragma unroll
    for (int s = 0; s < GH_KS; s++) {
        const float* gp = g_gh + (size_t)s * (3 * DH_) * B_;
        ghr += gp[d * B_ + b];
        ghz += gp[(DH_ + d) * B_ + b];
        ghn += gp[(2 * DH_ + d) * B_ + b];
    }
    float r = 1.0f / (1.0f + expf(-(gir + ghr)));
    float z = 1.0f / (1.0f + expf(-(giz + ghz)));
    float n = tanhf(gin + r * ghn);

    const float* hTin = parity ? g_hTB : g_hTA;
    float* hTout = parity ? g_hTA : g_hTB;
    float* hnext = parity ? g_hA  : g_hB;

    float hpv = hTin[d * B_ + b];
    float hn = (1.0f - z) * n + z * hpv;
    hnext[b * DH_ + d] = hn;
    hTout[d * B_ + b]  = hn;
}

// ---------------- per step: logits GEMM (fp32 via f32x2) + tile argmax ----------------
// grid = 250 blocks, 256 threads; tile 128v x 32b, thread = 2v x 8b (f32x2 over b-pairs)
__global__ void __launch_bounds__(256, 2)
k_logits(int parity, const float* __restrict__ Wo, const float* __restrict__ bo,
         float* __restrict__ out) {
    __shared__ float hs[128 * B_];          // 16 KB: k-chunk of hT [k_local][b]
    __shared__ float ls[TILE_V * 33];       // 16.5 KB: logits tile, padded

    const float* hT = parity ? g_hTA : g_hTB;   // h_new of this step

    int tid = threadIdx.x;
    int v0 = blockIdx.x * TILE_V;
    int vl = (tid >> 2) * 2;
    int bb = (tid & 3) * 8;

    const float* wrow0 = Wo + (size_t)(v0 + vl) * DH_;
    const float* wrow1 = wrow0 + DH_;

    unsigned long long a0[4] = {0ull, 0ull, 0ull, 0ull};
    unsigned long long a1[4] = {0ull, 0ull, 0ull, 0ull};

    for (int kc = 0; kc < DH_; kc += 128) {
        const float4* src = reinterpret_cast<const float4*>(hT + kc * B_);
        float4* dst = reinterpret_cast<float4*>(hs);
#pragma unroll
        for (int i = 0; i < 4; i++) dst[tid + 256 * i] = src[tid + 256 * i];
        __syncthreads();

        for (int kl = 0; kl < 128; kl += 4) {
            float4 w0 = *reinterpret_cast<const float4*>(wrow0 + kc + kl);
            float4 w1 = *reinterpret_cast<const float4*>(wrow1 + kc + kl);
            const float* w0p = reinterpret_cast<const float*>(&w0);
            const float* w1p = reinterpret_cast<const float*>(&w1);
#pragma unroll
            for (int kk = 0; kk < 4; kk++) {
                unsigned long long w0d, w1d;
                asm("mov.b64 %0, {%1,%1};" : "=l"(w0d) : "f"(w0p[kk]));
                asm("mov.b64 %0, {%1,%1};" : "=l"(w1d) : "f"(w1p[kk]));
                const unsigned long long* hrow =
                    reinterpret_cast<const unsigned long long*>(&hs[(kl + kk) * B_ + bb]);
#pragma unroll
                for (int j = 0; j < 4; j++) {
                    unsigned long long hv = hrow[j];
                    asm("fma.rn.f32x2 %0, %1, %2, %0;" : "+l"(a0[j]) : "l"(w0d), "l"(hv));
                    asm("fma.rn.f32x2 %0, %1, %2, %0;" : "+l"(a1[j]) : "l"(w1d), "l"(hv));
                }
            }
        }
        __syncthreads();
    }

    // epilogue: unpack + bias -> smem tile
    float bo0 = bo[v0 + vl], bo1 = bo[v0 + vl + 1];
#pragma unroll
    for (int j = 0; j < 4; j++) {
        float x0, x1, y0, y1;
        asm("mov.b64 {%0,%1}, %2;" : "=f"(x0), "=f"(x1) : "l"(a0[j]));
        asm("mov.b64 {%0,%1}, %2;" : "=f"(y0), "=f"(y1) : "l"(a1[j]));
        ls[vl * 33 + bb + 2 * j]           = x0 + bo0;
        ls[vl * 33 + bb + 2 * j + 1]       = x1 + bo0;
        ls[(vl + 1) * 33 + bb + 2 * j]     = y0 + bo1;
        ls[(vl + 1) * 33 + bb + 2 * j + 1] = y1 + bo1;
    }
    __syncthreads();

    // coalesced store: warp w covers batches w*4..w*4+3, lane strides v
    {
        int w = tid >> 5, l = tid & 31;
#pragma unroll
        for (int r = 0; r < 4; r++) {
            int b = w * 4 + r;
            float4 vv;
            vv.x = ls[(l * 4 + 0) * 33 + b];
            vv.y = ls[(l * 4 + 1) * 33 + b];
            vv.z = ls[(l * 4 + 2) * 33 + b];
            vv.w = ls[(l * 4 + 3) * 33 + b];
            *reinterpret_cast<float4*>(out + (size_t)b * V_ + v0 + l * 4) = vv;
        }
    }

    // per-(tile, b) argmax candidate (first-max tie-break: ascending scan, strict >)
    {
        int b = tid & 31, g = tid >> 5;
        float best = -3.4e38f; int besti = v0;
#pragma unroll
        for (int i = 0; i < 16; i++) {
            int vv = g * 16 + i;
            float val = ls[vv * 33 + b];
            if (val > best) { best = val; besti = v0 + vv; }
        }
        float* rv = hs;                       // reuse staging smem
        int*   ri = reinterpret_cast<int*>(hs + 256);
        rv[g * 32 + b] = best;
        ri[g * 32 + b] = besti;
        __syncthreads();
        if (tid < 32) {
            float bv = rv[tid]; int bi = ri[tid];
#pragma unroll
            for (int g2 = 1; g2 < 8; g2++) {
                float v2 = rv[g2 * 32 + tid];
                if (v2 > bv) { bv = v2; bi = ri[g2 * 32 + tid]; }
            }
            g_cval[blockIdx.x * B_ + tid] = bv;
            g_cidx[blockIdx.x * B_ + tid] = bi;
        }
    }
}

// ---------------- host ----------------
extern "C" void kernel_launch(void* const* d_in, const int* in_sizes, int n_in,
                              void* d_out, int out_size) {
    // metadata order: enc, [max_length, sos_token,] emb, W1, b1, W2, b2,
    //                 W_ih, b_ih, W_hh, b_hh, Wo, bo
    int base = n_in - 11;   // index of emb
    const float* enc  = (const float*)d_in[0];
    const int*   sosp = (n_in >= 14) ? (const int*)d_in[2] : nullptr;
    const float* emb  = (const float*)d_in[base + 0];
    const float* W1   = (const float*)d_in[base + 1];
    const float* b1   = (const float*)d_in[base + 2];
    const float* W2   = (const float*)d_in[base + 3];
    const float* b2   = (const float*)d_in[base + 4];
    const float* W_ih = (const float*)d_in[base + 5];
    const float* b_ih = (const float*)d_in[base + 6];
    const float* W_hh = (const float*)d_in[base + 7];
    const float* b_hh = (const float*)d_in[base + 8];
    const float* Wo   = (const float*)d_in[base + 9];
    const float* bo   = (const float*)d_in[base + 10];
    float* out = (float*)d_out;

    k_zero<<<64, 256>>>();
    k_encproj<<<S_, 256>>>(enc, W1, b1);

    for (int t = 0; t < MAXLEN_; t++) {
        int parity = t & 1;
        k_attn<<<B_, 256>>>(t, parity, enc, W1, W2, b2, emb, sosp, 1);
        k_ggemm<<<GG_BLOCKS, 256>>>(parity, W_ih, W_hh);
        k_comb<<<64, 256>>>(parity, b_ih, b_hh);
        k_logits<<<NBLK_B, 256>>>(parity, Wo, bo, out + (size_t)t * B_ * V_);
    }
}